// round 8
// baseline (speedup 1.0000x reference)
#include <cuda_runtime.h>
#include <cuda_bf16.h>

// QuantumConv2d on GB300 — direct tensor-product RX application (no WHT, no smem).
//
// Per 2x2 patch (x0,x1,x2,x3):
//   t_k = +-x0 +-x1 +-x2 +-x3  (sign + iff bit q of k set, LSB-first)
//   phase_k = -(t/2 + t^2/4)          [global phase dropped]
//   d_k = exp(i phase_k)
//   y = (RX(w3)(x)RX(w2)(x)RX(w1)(x)RX(w0)) d  as 4 commuting single-qubit
//       stages: pair (a, b=a^2^q): y_a = c a - i s b, y_b = -i s a + c b.
//       Packed (re,im): -i s b = (s*bi, -s*br) = (s,-s) .* swap(b)
//   0.25 initial-state amplitude folded into stage-3 coefficients.
//   state_{F(j)} = y_j, F = CNOT-ring perm {0,14,15,1,13,3,2,12,9,7,6,8,4,10,11,5}
//   out_q = sum_{j: bit(3-q) of F(j)} |y_j|^2 — accumulated as packed (re^2,im^2)
//   partial sums, single horizontal add per output at the end.

#define PK2(d, lo, hi)   asm("mov.b64 %0, {%1, %2};" : "=l"(d) : "f"(lo), "f"(hi))
#define UPK2(lo, hi, d)  asm("mov.b64 {%0, %1}, %2;" : "=f"(lo), "=f"(hi) : "l"(d))
#define ADD2(d, a, b)    asm("add.rn.f32x2 %0, %1, %2;" : "=l"(d) : "l"(a), "l"(b))
#define MUL2(d, a, b)    asm("mul.rn.f32x2 %0, %1, %2;" : "=l"(d) : "l"(a), "l"(b))
#define FMA2(d, a, b, c) asm("fma.rn.f32x2 %0, %1, %2, %3;" : "=l"(d) : "l"(a), "l"(b), "l"(c))

__global__ __launch_bounds__(256, 5) void qconv_kernel(const float* __restrict__ x,
                                                       const float* __restrict__ w,
                                                       float4* __restrict__ out) {
    // per-thread RX coefficients (w is uniform -> L1/L2 cached)
    float c[4], s[4];
    #pragma unroll
    for (int q = 0; q < 4; q++)
        __sincosf(0.5f * w[q], &s[q], &c[q]);
    c[3] *= 0.25f;   // fold |psi0| amplitude into last stage
    s[3] *= 0.25f;

    int tid = blockIdx.x * blockDim.x + threadIdx.x;   // = b*16384 + jj*128 + ii
    int b  = tid >> 14;
    int jj = (tid >> 7) & 127;
    int ii = tid & 127;

    const float* p = x + (b << 16) + (jj << 9) + (ii << 1);
    float2 a01 = *(const float2*)(p);
    float2 a23 = *(const float2*)(p + 256);
    float x0 = a01.x, x1 = a01.y, x2 = a23.x, x3 = a23.y;

    // t_k built from P/M/Q/R with FADD source-negation folding
    float P = x0 + x1, M = x0 - x1, Q = x2 + x3, R = x2 - x3;
    float t[16];
    t[0]  = -P - Q;  t[1]  =  M - Q;  t[2]  = -M - Q;  t[3]  =  P - Q;
    t[4]  =  R - P;  t[5]  =  M + R;  t[6]  =  R - M;  t[7]  =  P + R;
    t[8]  = -P - R;  t[9]  =  M - R;  t[10] = -M - R;  t[11] =  P - R;
    t[12] =  Q - P;  t[13] =  M + Q;  t[14] =  Q - M;  t[15] =  P + Q;

    // phases + cis
    unsigned long long v[16];   // packed (re, im)
    #pragma unroll
    for (int k = 0; k < 16; k++) {
        float ph = t[k] * fmaf(-0.25f, t[k], -0.5f);   // -(t/2 + t^2/4)
        float sn, cs;
        __sincosf(ph, &sn, &cs);
        PK2(v[k], cs, sn);
    }

    // 4 single-qubit RX stages (commuting)
    #pragma unroll
    for (int q = 0; q < 4; q++) {
        int m = 1 << q;
        float cq = c[q], sq = s[q], nsq = -s[q];
        unsigned long long C2, S2;
        PK2(C2, cq, cq);      // (c,  c)
        PK2(S2, sq, nsq);     // (s, -s)
        #pragma unroll
        for (int k = 0; k < 16; k++) {
            if (!(k & m)) {
                unsigned long long a = v[k], bb = v[k | m];
                float ar, ai, br, bi;
                UPK2(ar, ai, a);
                UPK2(br, bi, bb);
                unsigned long long sa, sb;        // swapped halves
                PK2(sa, ai, ar);
                PK2(sb, bi, br);
                unsigned long long ta, tb, ya, yb;
                MUL2(ta, a, C2);
                MUL2(tb, bb, C2);
                FMA2(ya, sb, S2, ta);             // c*a + (s*bi, -s*br)
                FMA2(yb, sa, S2, tb);             // c*b + (s*ai, -s*ar)
                v[k] = ya; v[k | m] = yb;
            }
        }
    }

    // packed squared magnitudes: sq[j] = (re^2, im^2)
    unsigned long long sq[16];
    #pragma unroll
    for (int j = 0; j < 16; j++)
        MUL2(sq[j], v[j], v[j]);

    // grouped packed accumulation through F = {0,14,15,1,13,3,2,12,9,7,6,8,4,10,11,5}
    // T_k: F(j)>>2 == k ; U_k: F(j)&3 == k
    unsigned long long T1p, T2p, T3p, U1p, U2p, U3p, tmp;
    ADD2(tmp, sq[9],  sq[10]); ADD2(T1p, tmp, sq[12]); ADD2(T1p, T1p, sq[15]);
    ADD2(tmp, sq[8],  sq[11]); ADD2(T2p, tmp, sq[13]); ADD2(T2p, T2p, sq[14]);
    ADD2(tmp, sq[1],  sq[2]);  ADD2(T3p, tmp, sq[4]);  ADD2(T3p, T3p, sq[7]);
    ADD2(tmp, sq[3],  sq[4]);  ADD2(U1p, tmp, sq[8]);  ADD2(U1p, U1p, sq[15]);
    ADD2(tmp, sq[1],  sq[6]);  ADD2(U2p, tmp, sq[10]); ADD2(U2p, U2p, sq[13]);
    ADD2(tmp, sq[2],  sq[5]);  ADD2(U3p, tmp, sq[9]);  ADD2(U3p, U3p, sq[14]);

    unsigned long long o0p, o1p, o2p, o3p;
    ADD2(o0p, T2p, T3p);   // bit 3 of F(j)
    ADD2(o1p, T1p, T3p);   // bit 2
    ADD2(o2p, U2p, U3p);   // bit 1
    ADD2(o3p, U1p, U3p);   // bit 0

    float lo, hi, o0, o1, o2, o3;
    UPK2(lo, hi, o0p); o0 = lo + hi;
    UPK2(lo, hi, o1p); o1 = lo + hi;
    UPK2(lo, hi, o2p); o2 = lo + hi;
    UPK2(lo, hi, o3p); o3 = lo + hi;

    out[tid] = make_float4(o0, o1, o2, o3);
}

extern "C" void kernel_launch(void* const* d_in, const int* in_sizes, int n_in,
                              void* d_out, int out_size) {
    const float* x = (const float*)d_in[0];
    const float* w = (const float*)d_in[1];
    if (n_in >= 2 && in_sizes[0] == 4) {   // robustness if metadata order differs
        x = (const float*)d_in[1];
        w = (const float*)d_in[0];
    }
    qconv_kernel<<<4096, 256>>>(x, w, (float4*)d_out);
}

// round 9
// speedup vs baseline: 1.0406x; 1.0406x over previous
#include <cuda_runtime.h>
#include <cuda_bf16.h>

// QuantumConv2d on GB300 — direct tensor-product RX application (no WHT, no smem).
//
// Per 2x2 patch (x0,x1,x2,x3):
//   t_k = +-x0 +-x1 +-x2 +-x3  (sign + iff bit q of k set, LSB-first)
//   phase_k = -(t/2 + t^2/4)          [global phase dropped]
//   d_k = exp(i phase_k)
//   y = (RX(w3)(x)RX(w2)(x)RX(w1)(x)RX(w0)) d  as 4 commuting single-qubit
//       stages: pair (a, b=a^2^q): y_a = c a - i s b, y_b = -i s a + c b.
//       Packed (re,im): -i s b = (s*bi, -s*br) = (s,-s) .* swap(b)
//   0.25 initial-state amplitude folded into stage-3 coefficients.
//   state_{F(j)} = y_j, F = CNOT-ring perm {0,14,15,1,13,3,2,12,9,7,6,8,4,10,11,5}
//   out_q = sum_{j: bit(3-q) of F(j)} |y_j|^2  (wide scalar accumulation — the
//   packed/serial variant measured slower in R8).

#define PK2(d, lo, hi)   asm("mov.b64 %0, {%1, %2};" : "=l"(d) : "f"(lo), "f"(hi))
#define UPK2(lo, hi, d)  asm("mov.b64 {%0, %1}, %2;" : "=f"(lo), "=f"(hi) : "l"(d))
#define MUL2(d, a, b)    asm("mul.rn.f32x2 %0, %1, %2;" : "=l"(d) : "l"(a), "l"(b))
#define FMA2(d, a, b, c) asm("fma.rn.f32x2 %0, %1, %2, %3;" : "=l"(d) : "l"(a), "l"(b), "l"(c))

__global__ __launch_bounds__(256) void qconv_kernel(const float* __restrict__ x,
                                                    const float* __restrict__ w,
                                                    float4* __restrict__ out) {
    // per-thread RX coefficients (w is uniform -> L1/L2 cached)
    float c[4], s[4];
    #pragma unroll
    for (int q = 0; q < 4; q++)
        __sincosf(0.5f * w[q], &s[q], &c[q]);
    c[3] *= 0.25f;   // fold |psi0| amplitude into last stage
    s[3] *= 0.25f;

    int tid = blockIdx.x * blockDim.x + threadIdx.x;   // = b*16384 + jj*128 + ii
    int b  = tid >> 14;
    int jj = (tid >> 7) & 127;
    int ii = tid & 127;

    const float* p = x + (b << 16) + (jj << 9) + (ii << 1);
    float2 a01 = *(const float2*)(p);
    float2 a23 = *(const float2*)(p + 256);
    float x0 = a01.x, x1 = a01.y, x2 = a23.x, x3 = a23.y;

    // t_k from P/M/Q/R (FADD source-negation folds)
    float P = x0 + x1, M = x0 - x1, Q = x2 + x3, R = x2 - x3;
    float t[16];
    t[0]  = -P - Q;  t[1]  =  M - Q;  t[2]  = -M - Q;  t[3]  =  P - Q;
    t[4]  =  R - P;  t[5]  =  M + R;  t[6]  =  R - M;  t[7]  =  P + R;
    t[8]  = -P - R;  t[9]  =  M - R;  t[10] = -M - R;  t[11] =  P - R;
    t[12] =  Q - P;  t[13] =  M + Q;  t[14] =  Q - M;  t[15] =  P + Q;

    unsigned long long C_N025, C_N05;
    asm("mov.b64 %0, 0xBE800000BE800000;" : "=l"(C_N025));  // (-0.25, -0.25)
    asm("mov.b64 %0, 0xBF000000BF000000;" : "=l"(C_N05));   // (-0.5,  -0.5)

    // packed phase polynomial: ph = t * (-0.25 t - 0.5), 2 packed ops per pair;
    // 16 independent sincos chains follow (ILP preserved)
    unsigned long long v[16];   // packed (re, im)
    #pragma unroll
    for (int k = 0; k < 16; k += 2) {
        unsigned long long tp, f, ph2;
        PK2(tp, t[k], t[k + 1]);
        FMA2(f, tp, C_N025, C_N05);
        MUL2(ph2, tp, f);
        float pa, pb;
        UPK2(pa, pb, ph2);
        float s0, c0, s1, c1;
        __sincosf(pa, &s0, &c0);
        __sincosf(pb, &s1, &c1);
        PK2(v[k],     c0, s0);
        PK2(v[k + 1], c1, s1);
    }

    // 4 single-qubit RX stages (commuting)
    #pragma unroll
    for (int q = 0; q < 4; q++) {
        int m = 1 << q;
        float cq = c[q], sq = s[q], nsq = -s[q];
        unsigned long long C2, S2;
        PK2(C2, cq, cq);      // (c,  c)
        PK2(S2, sq, nsq);     // (s, -s)
        #pragma unroll
        for (int k = 0; k < 16; k++) {
            if (!(k & m)) {
                unsigned long long a = v[k], bb = v[k | m];
                float ar, ai, br, bi;
                UPK2(ar, ai, a);
                UPK2(br, bi, bb);
                unsigned long long sa, sb;        // swapped halves
                PK2(sa, ai, ar);
                PK2(sb, bi, br);
                unsigned long long ta, tb, ya, yb;
                MUL2(ta, a, C2);
                MUL2(tb, bb, C2);
                FMA2(ya, sb, S2, ta);             // c*a + (s*bi, -s*br)
                FMA2(yb, sa, S2, tb);             // c*b + (s*ai, -s*ar)
                v[k] = ya; v[k | m] = yb;
            }
        }
    }

    // probabilities (scalar, wide ILP)
    float pr[16];
    #pragma unroll
    for (int j = 0; j < 16; j++) {
        float re, im;
        UPK2(re, im, v[j]);
        pr[j] = fmaf(re, re, im * im);
    }

    // grouped accumulation through F = {0,14,15,1,13,3,2,12,9,7,6,8,4,10,11,5}
    float T1 = pr[9]  + pr[10] + pr[12] + pr[15];
    float T2 = pr[8]  + pr[11] + pr[13] + pr[14];
    float T3 = pr[1]  + pr[2]  + pr[4]  + pr[7];
    float U1 = pr[3]  + pr[4]  + pr[8]  + pr[15];
    float U2 = pr[1]  + pr[6]  + pr[10] + pr[13];
    float U3 = pr[2]  + pr[5]  + pr[9]  + pr[14];
    float o0 = T2 + T3;   // bit 3 of F(j)
    float o1 = T1 + T3;   // bit 2
    float o2 = U2 + U3;   // bit 1
    float o3 = U1 + U3;   // bit 0

    out[tid] = make_float4(o0, o1, o2, o3);
}

extern "C" void kernel_launch(void* const* d_in, const int* in_sizes, int n_in,
                              void* d_out, int out_size) {
    const float* x = (const float*)d_in[0];
    const float* w = (const float*)d_in[1];
    if (n_in >= 2 && in_sizes[0] == 4) {   // robustness if metadata order differs
        x = (const float*)d_in[1];
        w = (const float*)d_in[0];
    }
    qconv_kernel<<<4096, 256>>>(x, w, (float4*)d_out);
}